// round 10
// baseline (speedup 1.0000x reference)
#include <cuda_runtime.h>
#include <cstddef>

// ---------------------------------------------------------------------------
// DiffJPEG: per 8x8 block  ->  D X D^T  ->  round(x/Q)*Q  ->  D^T X' D
// Input/Output: (32, 3, 512, 512) float32, contiguous.
//
// 8 lanes per block: lane l owns row l (8 floats). All 8-pt transforms are
// lane-local with immediate-constant E/O matvecs (R3 shape). The two 8x8
// transposes use a per-group smem slot (72-float stride: conflict-free
// scatter store, LDS.128 gather) + __syncwarp. No divergence anywhere.
// Working set ~46 regs -> __launch_bounds__(256,5) -> 40 warps/SM, breaking
// the 3-CTA occupancy ceiling of the 1-thread-per-block layout (R3..R8 all
// showed latency-exposure bound at occ~31%).
// (Resubmission of R9 — container infra failure, kernel unchanged.)
// ---------------------------------------------------------------------------

__host__ __device__ constexpr float COS9(int m) {
    constexpr float t[9] = {
        1.0f,
        0.9807852804032304f,
        0.9238795325112868f,
        0.8314696123025452f,
        0.7071067811865476f,
        0.5555702330196022f,
        0.3826834323650898f,
        0.1950903220161283f,
        0.0f
    };
    return t[m];
}

__host__ __device__ constexpr float cos16f(int m) {
    m &= 31;
    if (m <= 8)  return  COS9(m);
    if (m <= 16) return -COS9(16 - m);
    if (m <= 24) return -COS9(m - 16);
    return COS9(32 - m);
}

struct Mat8 { float v[8][8]; };
struct Mat4 { float v[4][4]; };

__host__ __device__ constexpr Mat8 makeD() {
    Mat8 d{};
    for (int i = 0; i < 8; i++)
        for (int j = 0; j < 8; j++)
            d.v[i][j] = (i == 0 ? 0.35355339059327373f : 0.5f) * cos16f((2 * j + 1) * i);
    return d;
}

__host__ __device__ constexpr Mat4 makeE() {
    Mat4 e{};
    constexpr Mat8 d = makeD();
    for (int k = 0; k < 4; k++)
        for (int j = 0; j < 4; j++)
            e.v[k][j] = d.v[2 * k][j];
    return e;
}
__host__ __device__ constexpr Mat4 makeO() {
    Mat4 o{};
    constexpr Mat8 d = makeD();
    for (int k = 0; k < 4; k++)
        for (int j = 0; j < 4; j++)
            o.v[k][j] = d.v[2 * k + 1][j];
    return o;
}

// quality=50 -> scale=100 -> Q is exactly the integer luma table
__host__ __device__ constexpr Mat8 makeQ() {
    Mat8 q{};
    constexpr float t[8][8] = {
        {16, 11, 10, 16, 24, 40, 51, 61},
        {12, 12, 14, 19, 26, 58, 60, 55},
        {14, 13, 16, 24, 40, 57, 69, 56},
        {14, 17, 22, 29, 51, 87, 80, 62},
        {18, 22, 37, 56, 68, 109, 103, 77},
        {24, 35, 55, 64, 81, 104, 113, 92},
        {49, 64, 78, 87, 103, 121, 120, 101},
        {72, 92, 95, 98, 112, 100, 103, 99}};
    for (int i = 0; i < 8; i++)
        for (int j = 0; j < 8; j++)
            q.v[i][j] = t[i][j];
    return q;
}

// Transposed tables: row l holds column l of Q / 1/Q  (lane-indexed access)
__host__ __device__ constexpr Mat8 makeQT() {
    Mat8 qt{};
    constexpr Mat8 q = makeQ();
    for (int l = 0; l < 8; l++)
        for (int i = 0; i < 8; i++)
            qt.v[l][i] = q.v[i][l];
    return qt;
}
__host__ __device__ constexpr Mat8 makeQiT() {
    Mat8 qt{};
    constexpr Mat8 q = makeQ();
    for (int l = 0; l < 8; l++)
        for (int i = 0; i < 8; i++)
            qt.v[l][i] = 1.0f / q.v[i][l];
    return qt;
}

__constant__ Mat8 QT_c  = makeQT();
__constant__ Mat8 QiT_c = makeQiT();

constexpr int W         = 512;
constexpr int H         = 512;
constexpr int IMG_ELEMS = H * W;          // 262144
constexpr float RMAGIC  = 12582912.0f;    // 1.5 * 2^23 : round-half-even magic

// out[i] = sum_j D[i][j] x[j]   (36 FMA-pipe ops, immediate constants)
__device__ __forceinline__ void dct8_fwd(const float x[8], float out[8]) {
    constexpr Mat4 E = makeE();
    constexpr Mat4 O = makeO();
    float s[4], d[4];
    #pragma unroll
    for (int j = 0; j < 4; j++) {
        s[j] = x[j] + x[7 - j];
        d[j] = x[j] - x[7 - j];
    }
    #pragma unroll
    for (int k = 0; k < 4; k++) {
        float se = s[0] * E.v[k][0];
        float so = d[0] * O.v[k][0];
        #pragma unroll
        for (int j = 1; j < 4; j++) {
            se += s[j] * E.v[k][j];
            so += d[j] * O.v[k][j];
        }
        out[2 * k]     = se;
        out[2 * k + 1] = so;
    }
}

// out[j] = sum_i D[i][j] f[i]
__device__ __forceinline__ void dct8_inv(const float f[8], float out[8]) {
    constexpr Mat4 E = makeE();
    constexpr Mat4 O = makeO();
    #pragma unroll
    for (int j = 0; j < 4; j++) {
        float e = f[0] * E.v[0][j];
        float o = f[1] * O.v[0][j];
        #pragma unroll
        for (int k = 1; k < 4; k++) {
            e += f[2 * k]     * E.v[k][j];
            o += f[2 * k + 1] * O.v[k][j];
        }
        out[j]     = e + o;
        out[7 - j] = e - o;
    }
}

// 8x8 transpose among the 8 lanes of a group via the group's 72-float smem
// slot. Scatter-store transposed (conflict-free: banks 8g+8c+l distinct per
// instruction), gather rows with 2x LDS.128 (benign 2-way phase conflict).
__device__ __forceinline__ void transpose8(float v[8], float* __restrict__ sb, int l) {
    #pragma unroll
    for (int c = 0; c < 8; c++)
        sb[c * 8 + l] = v[c];
    __syncwarp();
    float4 A = *reinterpret_cast<const float4*>(sb + l * 8);
    float4 B = *reinterpret_cast<const float4*>(sb + l * 8 + 4);
    v[0] = A.x; v[1] = A.y; v[2] = A.z; v[3] = A.w;
    v[4] = B.x; v[5] = B.y; v[6] = B.z; v[7] = B.w;
    __syncwarp();   // protect slot reuse by the second transpose
}

__global__ void __launch_bounds__(256, 5)
diffjpeg_kernel(const float* __restrict__ in, float* __restrict__ out, int nblocks) {
    __shared__ __align__(16) float sbuf[8][4][72];  // [warp][group][block slot]

    int tid  = threadIdx.x;
    int lane = tid & 31;
    int l    = lane & 7;        // row within block
    int g    = lane >> 3;       // block within warp
    int warp = tid >> 5;

    int blk = (blockIdx.x * 8 + warp) * 4 + g;   // exact grid: always < nblocks

    int img = blk >> 12;        // 4096 blocks per image
    int rem = blk & 4095;
    int br  = rem >> 6;
    int bc  = rem & 63;

    size_t base = (size_t)img * IMG_ELEMS + (size_t)br * 8 * W
                + (size_t)bc * 8 + (size_t)l * W;
    const float* src = in + base;
    float* dst = out + base;

    float* sb = sbuf[warp][g];

    // lane-indexed quantizer columns (loaded once)
    float qi[8], qq[8];
    {
        const float4* p = reinterpret_cast<const float4*>(QiT_c.v[l]);
        float4 A = p[0], B = p[1];
        qi[0] = A.x; qi[1] = A.y; qi[2] = A.z; qi[3] = A.w;
        qi[4] = B.x; qi[5] = B.y; qi[6] = B.z; qi[7] = B.w;
        const float4* q = reinterpret_cast<const float4*>(QT_c.v[l]);
        float4 C = q[0], Dd = q[1];
        qq[0] = C.x; qq[1] = C.y; qq[2] = C.z; qq[3] = C.w;
        qq[4] = Dd.x; qq[5] = Dd.y; qq[6] = Dd.z; qq[7] = Dd.w;
    }

    // ---- load row l of own block (warp: 4 adjacent blocks -> full 128B lines)
    float4 a = __ldcs(reinterpret_cast<const float4*>(src));
    float4 b = __ldcs(reinterpret_cast<const float4*>(src + 4));
    float v[8] = {a.x, a.y, a.z, a.w, b.x, b.y, b.z, b.w};

    float u[8];
    dct8_fwd(v, u);        // row DCT: u[j] = T[l][j]
    transpose8(u, sb, l);  // u[i] = T[i][l]  (column l)

    float f[8];
    dct8_fwd(u, f);        // f[i] = (D X D^T)[i][l]

    // quantize column l: round-half-even(f * 1/Q) * Q   (exact rintf semantics)
    #pragma unroll
    for (int i = 0; i < 8; i++) {
        float p  = f[i] * qi[i];
        float r1 = __fadd_rn(p, RMAGIC);
        float r2 = __fadd_rn(r1, -RMAGIC);
        f[i] = r2 * qq[i];
    }

    dct8_inv(f, u);        // u[r] = G[r][l]  (column IDCT)
    transpose8(u, sb, l);  // u[j] = G[l][j]  (row l)

    float y[8];
    dct8_inv(u, y);        // row IDCT

    __stcs(reinterpret_cast<float4*>(dst),     make_float4(y[0], y[1], y[2], y[3]));
    __stcs(reinterpret_cast<float4*>(dst + 4), make_float4(y[4], y[5], y[6], y[7]));
}

extern "C" void kernel_launch(void* const* d_in, const int* in_sizes, int n_in,
                              void* d_out, int out_size) {
    const float* in = (const float*)d_in[0];
    float* out = (float*)d_out;
    int nblocks = in_sizes[0] / 64;     // 393216
    int nthreads = nblocks * 8;         // 8 lanes per block
    int grid = nthreads / 256;          // 12288, exact
    diffjpeg_kernel<<<grid, 256>>>(in, out, nblocks);
}

// round 11
// speedup vs baseline: 1.5606x; 1.5606x over previous
#include <cuda_runtime.h>
#include <cstddef>
#include <cstdint>

// ---------------------------------------------------------------------------
// DiffJPEG: per 8x8 block  ->  D X D^T  ->  round(x/Q)*Q  ->  D^T X' D
// Input/Output: (32, 3, 512, 512) float32, contiguous.
//
// One thread per 8x8 block (R8 compute core, Q folded into immediates), but
// input is staged through shared memory with cp.async:
//   - each CTA owns a contiguous 64KB span (256 blocks = 32 image rows)
//   - 16x cp.async.cg 16B per thread, dst remapped BLOCK-MAJOR with 272B
//     per-block stride (17 chunks): thread t's block is contiguous at
//     smem + t*272, and LDS.128 banks (17t+2r+h) mod 8 are conflict-free
//   - one wait_group+__syncthreads per CTA replaces per-thread 577-cycle
//     LDG scoreboard stalls (R8's measured ~14us latency exposure)
// smem 69632B x 3 CTAs = 204KB; regs ~80 -> 3 CTAs/SM.
// ---------------------------------------------------------------------------

__host__ __device__ constexpr float COS9(int m) {
    constexpr float t[9] = {
        1.0f,
        0.9807852804032304f,
        0.9238795325112868f,
        0.8314696123025452f,
        0.7071067811865476f,
        0.5555702330196022f,
        0.3826834323650898f,
        0.1950903220161283f,
        0.0f
    };
    return t[m];
}

__host__ __device__ constexpr float cos16f(int m) {
    m &= 31;
    if (m <= 8)  return  COS9(m);
    if (m <= 16) return -COS9(16 - m);
    if (m <= 24) return -COS9(m - 16);
    return COS9(32 - m);
}

struct Mat8 { float v[8][8]; };
struct Mat4 { float v[4][4]; };

__host__ __device__ constexpr Mat8 makeD() {
    Mat8 d{};
    for (int i = 0; i < 8; i++)
        for (int j = 0; j < 8; j++)
            d.v[i][j] = (i == 0 ? 0.35355339059327373f : 0.5f) * cos16f((2 * j + 1) * i);
    return d;
}

__host__ __device__ constexpr Mat4 makeE() {
    Mat4 e{};
    constexpr Mat8 d = makeD();
    for (int k = 0; k < 4; k++)
        for (int j = 0; j < 4; j++)
            e.v[k][j] = d.v[2 * k][j];
    return e;
}
__host__ __device__ constexpr Mat4 makeO() {
    Mat4 o{};
    constexpr Mat8 d = makeD();
    for (int k = 0; k < 4; k++)
        for (int j = 0; j < 4; j++)
            o.v[k][j] = d.v[2 * k + 1][j];
    return o;
}

// quality=50 -> scale=100 -> Q is exactly the integer luma table
__host__ __device__ constexpr Mat8 makeQ() {
    Mat8 q{};
    constexpr float t[8][8] = {
        {16, 11, 10, 16, 24, 40, 51, 61},
        {12, 12, 14, 19, 26, 58, 60, 55},
        {14, 13, 16, 24, 40, 57, 69, 56},
        {14, 17, 22, 29, 51, 87, 80, 62},
        {18, 22, 37, 56, 68, 109, 103, 77},
        {24, 35, 55, 64, 81, 104, 113, 92},
        {49, 64, 78, 87, 103, 121, 120, 101},
        {72, 92, 95, 98, 112, 100, 103, 99}};
    for (int i = 0; i < 8; i++)
        for (int j = 0; j < 8; j++)
            q.v[i][j] = t[i][j];
    return q;
}

__host__ __device__ constexpr Mat8 makeQinv() {
    Mat8 qi{};
    constexpr Mat8 q = makeQ();
    for (int i = 0; i < 8; i++)
        for (int j = 0; j < 8; j++)
            qi.v[i][j] = 1.0f / q.v[i][j];
    return qi;
}

constexpr int W          = 512;
constexpr int CTA_FLOATS = 16384;          // 64KB span per CTA (256 blocks)
constexpr int BLK_STRIDE = 68;             // floats per block slot (272B = 17 chunks)
constexpr int SMEM_BYTES = 256 * BLK_STRIDE * 4;   // 69632
constexpr float RMAGIC   = 12582912.0f;    // 1.5 * 2^23 : round-half-even magic

// Forward 8-pt DCT-II (R3/R8 matvec shape), output i scaled by q_i (all q's
// compile-time -> immediate-constant FFMA).
__device__ __forceinline__ void dct8_fwd_q(
    const float x[8], float out[8],
    float q0, float q1, float q2, float q3,
    float q4, float q5, float q6, float q7)
{
    constexpr Mat4 E = makeE();
    constexpr Mat4 O = makeO();
    const float qe[4] = {q0, q2, q4, q6};
    const float qo[4] = {q1, q3, q5, q7};
    float s[4], d[4];
    #pragma unroll
    for (int j = 0; j < 4; j++) {
        s[j] = x[j] + x[7 - j];
        d[j] = x[j] - x[7 - j];
    }
    #pragma unroll
    for (int k = 0; k < 4; k++) {
        float se = s[0] * (E.v[k][0] * qe[k]);
        float so = d[0] * (O.v[k][0] * qo[k]);
        #pragma unroll
        for (int j = 1; j < 4; j++) {
            se += s[j] * (E.v[k][j] * qe[k]);
            so += d[j] * (O.v[k][j] * qo[k]);
        }
        out[2 * k]     = se;
        out[2 * k + 1] = so;
    }
}

// Inverse: out[j] = sum_i D[i][j] * (q_i * f[i])
__device__ __forceinline__ void dct8_inv_q(
    const float f[8], float out[8],
    float q0, float q1, float q2, float q3,
    float q4, float q5, float q6, float q7)
{
    constexpr Mat4 E = makeE();
    constexpr Mat4 O = makeO();
    const float qe[4] = {q0, q2, q4, q6};
    const float qo[4] = {q1, q3, q5, q7};
    #pragma unroll
    for (int j = 0; j < 4; j++) {
        float e = f[0] * (E.v[0][j] * qe[0]);
        float o = f[1] * (O.v[0][j] * qo[0]);
        #pragma unroll
        for (int k = 1; k < 4; k++) {
            e += f[2 * k]     * (E.v[k][j] * qe[k]);
            o += f[2 * k + 1] * (O.v[k][j] * qo[k]);
        }
        out[j]     = e + o;
        out[7 - j] = e - o;
    }
}

__device__ __forceinline__ void cp_async16(uint32_t dst_smem, const void* src) {
    asm volatile("cp.async.cg.shared.global [%0], [%1], 16;"
                 :: "r"(dst_smem), "l"(src) : "memory");
}

__global__ void __launch_bounds__(256, 3)
diffjpeg_kernel(const float* __restrict__ in, float* __restrict__ out) {
    extern __shared__ __align__(16) float smem[];

    constexpr Mat8 Q  = makeQ();
    constexpr Mat8 Qi = makeQinv();

    const int tid = threadIdx.x;
    const int cta = blockIdx.x;
    const size_t cta_base = (size_t)cta * CTA_FLOATS;
    const float* gsrc = in + cta_base;

    // ---- stage 64KB into smem, block-major with 17-chunk stride ----
    uint32_t sbase = (uint32_t)__cvta_generic_to_shared(smem);
    #pragma unroll
    for (int i = 0; i < 16; i++) {
        int g  = tid + i * 256;       // 16B chunk index within CTA span
        int ri = g >> 7;              // image row within span (0..31)
        int wi = g & 127;             // 16B chunk within row (0..127)
        int b  = ((ri >> 3) << 6) | (wi >> 1);         // local block id
        int slot = b * 17 + ((ri & 7) << 1) + (wi & 1); // 16B slot in smem
        cp_async16(sbase + (uint32_t)slot * 16, gsrc + (size_t)g * 4);
    }
    asm volatile("cp.async.commit_group;" ::: "memory");
    asm volatile("cp.async.wait_group 0;" ::: "memory");
    __syncthreads();

    // ---- thread t owns block t: contiguous 68-float slot ----
    const float* sb = smem + tid * BLK_STRIDE;

    float T[8][8];

    // Phase 1: row DCT from smem (conflict-free LDS.128)
    #pragma unroll
    for (int r = 0; r < 8; r++) {
        float4 A = *reinterpret_cast<const float4*>(sb + r * 8);
        float4 B = *reinterpret_cast<const float4*>(sb + r * 8 + 4);
        float x[8] = {A.x, A.y, A.z, A.w, B.x, B.y, B.z, B.w};
        dct8_fwd_q(x, T[r], 1.f, 1.f, 1.f, 1.f, 1.f, 1.f, 1.f, 1.f);
    }

    // Phase 2: per column j: (D·)/Q -> round-half-even -> (D^T·)*Q
    #pragma unroll
    for (int j = 0; j < 8; j++) {
        float col[8], f[8];
        #pragma unroll
        for (int r = 0; r < 8; r++) col[r] = T[r][j];
        dct8_fwd_q(col, f,
                   Qi.v[0][j], Qi.v[1][j], Qi.v[2][j], Qi.v[3][j],
                   Qi.v[4][j], Qi.v[5][j], Qi.v[6][j], Qi.v[7][j]);
        #pragma unroll
        for (int i = 0; i < 8; i++) {
            float r1 = __fadd_rn(f[i], RMAGIC);
            f[i] = __fadd_rn(r1, -RMAGIC);
        }
        dct8_inv_q(f, col,
                   Q.v[0][j], Q.v[1][j], Q.v[2][j], Q.v[3][j],
                   Q.v[4][j], Q.v[5][j], Q.v[6][j], Q.v[7][j]);
        #pragma unroll
        for (int r = 0; r < 8; r++) T[r][j] = col[r];
    }

    // Phase 3: row inverse + streaming store (same global layout as input)
    const int rb = tid >> 6;      // local block row (0..3)
    const int bc = tid & 63;      // block col (0..63)
    float* dstb = out + cta_base + (size_t)bc * 8;
    #pragma unroll
    for (int r = 0; r < 8; r++) {
        float y[8];
        dct8_inv_q(T[r], y, 1.f, 1.f, 1.f, 1.f, 1.f, 1.f, 1.f, 1.f);
        float* p = dstb + (size_t)(rb * 8 + r) * W;
        __stcs(reinterpret_cast<float4*>(p),     make_float4(y[0], y[1], y[2], y[3]));
        __stcs(reinterpret_cast<float4*>(p + 4), make_float4(y[4], y[5], y[6], y[7]));
    }
}

extern "C" void kernel_launch(void* const* d_in, const int* in_sizes, int n_in,
                              void* d_out, int out_size) {
    const float* in = (const float*)d_in[0];
    float* out = (float*)d_out;
    int nctas = in_sizes[0] / CTA_FLOATS;   // 1536
    cudaFuncSetAttribute(diffjpeg_kernel,
                         cudaFuncAttributeMaxDynamicSharedMemorySize, SMEM_BYTES);
    diffjpeg_kernel<<<nctas, 256, SMEM_BYTES>>>(in, out);
}